// round 13
// baseline (speedup 1.0000x reference)
#include <cuda_runtime.h>

// FINAL — at the single-launch replay floor. Reference math collapses exactly:
//   p1 has feature dim 1  ->  mu == p1 (exact, mean over a singleton axis)
//   (p1 - mu) == 0 exactly -> var == 0 exactly
//   out = 0/sqrt(eps) * ln_weight + ln_bias = ln_bias  (for ANY x/params/ln_weight)
// So out[b] = ln_bias[0] for all b. ln_bias is read from device memory so the
// kernel is correct for arbitrary bias values, not just the test seed.
//
// Variance ledger for this EXACT source: wall {4.576 x2, 5.920, 5.76, 12.096}
// us vs node {3.68, 3.65, 4.10, 3.84, 3.78} us. Node stable; wall is a
// heavy-tailed harness-side variable uncorrelated with source. 4.576 us is
// the best wall quantum observed (hit 4/9 runs, all by this family).
// Work is provably minimal: one L2-hit load + 2 KB coalesced stores in a
// single mandatory kernel node (no broadcast-capable memcpy/memset under
// graph-capture rules; host readback would need a sync). Holding position.

__global__ __launch_bounds__(256, 1)
void QuantumGate_65481071410733_kernel(const float* __restrict__ ln_bias,
                                       float* __restrict__ out,
                                       int n) {
    int i = blockIdx.x * blockDim.x + threadIdx.x;
    if (i < n) {
        out[i] = __ldg(ln_bias);
    }
}

extern "C" void kernel_launch(void* const* d_in, const int* in_sizes, int n_in,
                              void* d_out, int out_size) {
    // Input order per metadata: x, params, ln_weight, ln_bias
    const float* ln_bias = (const float*)d_in[3];
    float* out = (float*)d_out;
    int n = out_size;  // 512
    QuantumGate_65481071410733_kernel<<<(n + 255) / 256, 256>>>(ln_bias, out, n);
}

// round 14
// speedup vs baseline: 1.3007x; 1.3007x over previous
#include <cuda_runtime.h>

// FINAL — at the single-launch replay floor. Reference math collapses exactly:
//   p1 has feature dim 1  ->  mu == p1 (exact, mean over a singleton axis)
//   (p1 - mu) == 0 exactly -> var == 0 exactly
//   out = 0/sqrt(eps) * ln_weight + ln_bias = ln_bias  (for ANY x/params/ln_weight)
// So out[b] = ln_bias[0] for all b. ln_bias is read from device memory so the
// kernel is correct for arbitrary bias values, not just the test seed.
//
// Variance ledger for this EXACT source: wall {4.576 x2, 5.76, 5.92, 5.952,
// 12.096} us vs node {3.62-4.10} us. Node stable and decoupled from wall;
// wall is a heavy-tailed harness-side variable uncorrelated with source.
// 4.576 us is the best observed quantum, hit only by this family (4/11 runs).
// Work is provably minimal: one L2-hit load + 2 KB coalesced stores in a
// single mandatory kernel node (no broadcast-capable memcpy/memset under
// graph-capture rules; host readback would need a sync). Holding position.

__global__ __launch_bounds__(256, 1)
void QuantumGate_65481071410733_kernel(const float* __restrict__ ln_bias,
                                       float* __restrict__ out,
                                       int n) {
    int i = blockIdx.x * blockDim.x + threadIdx.x;
    if (i < n) {
        out[i] = __ldg(ln_bias);
    }
}

extern "C" void kernel_launch(void* const* d_in, const int* in_sizes, int n_in,
                              void* d_out, int out_size) {
    // Input order per metadata: x, params, ln_weight, ln_bias
    const float* ln_bias = (const float*)d_in[3];
    float* out = (float*)d_out;
    int n = out_size;  // 512
    QuantumGate_65481071410733_kernel<<<(n + 255) / 256, 256>>>(ln_bias, out, n);
}